// round 14
// baseline (speedup 1.0000x reference)
#include <cuda_runtime.h>

#define NB 16384
#define N1 1024
#define K1 512
#define N2 512
#define K2 1024
#define NCTA 304
#define NPREP 304
#define RPTOT (N1*K1 + N2*K2)        // 1048576 repack elements
#define RPSLICE 3450                 // ceil(RPTOT/304)
#define NT1 1024                     // G1: 128 rowblocks x 8 ntiles (128x128,K512)
#define NHALF 320                    // G2 tiles u<320: 2 K-halves
#define NQT 192                      // G2 tiles u>=320: 4 K-quarters + combine
#define T1B  NPREP                   // 304
#define T2AB (NPREP + NT1)           // 1328: halfA
#define T2BB (T2AB + NHALF)          // 1648: halfB
#define QB   (T2BB + NHALF)          // 1968: quarters (192*4 = 768)
#define CB   (QB + 4 * NQT)          // 2736: combines (192)
#define NTILES (CB + NQT)            // 2928

// ---------------- device-global scratch (no allocations) -------------------
__device__ float g_W1p[N1 * K1];
__device__ float g_W2p[N2 * K2];
__device__ float g_h[(size_t)NB * N1];
__device__ float g_beff1[N1], g_beff2[N2], g_c[N1];
__device__ float g_p[4][(size_t)NB * N2];      // quarter partials (rows >= 10240 used)
__device__ float g_tq[4][NB];                  // quarter trace partials
__device__ int   g_q;
__device__ int   g_prep_done;
__device__ int   g_ready[NB / 128];
__device__ int   g_half[NHALF];
__device__ int   g_qc[NQT];

// ---------------- init (graph-replay-safe reset) ---------------------------
__global__ void init_k() {
    int i = blockIdx.x * 256 + threadIdx.x;
    if (i == 0) { g_q = 0; g_prep_done = 0; }
    if (i < NB / 128) g_ready[i] = 0;
    if (i < NHALF) g_half[i] = 0;
    if (i < NQT) g_qc[i] = 0;
}

// ---------------- prep slice (runs inside persistent kernel) ---------------
__device__ void prep_slice(int s, int tid, float* cred,
                           const float* __restrict__ t,
                           const float* __restrict__ W1, const float* __restrict__ b1,
                           const float* __restrict__ W2, const float* __restrict__ b2) {
    int end = min((s + 1) * RPSLICE, RPTOT);
    for (int i = s * RPSLICE + tid; i < end; i += 256) {
        if (i < N1 * K1) {
            int n = i >> 9, k = i & 511;
            g_W1p[i] = W1[n * 513 + k];
        } else {
            int j = i - N1 * K1;
            int n = j >> 10, k = j & 1023;
            g_W2p[j] = W2[n * 1025 + k];
        }
    }
    {
        int jj = s * 4 + (tid >> 6);
        int ks = tid & 63;
        float p = 0.f;
        if (jj < N1) {
            #pragma unroll
            for (int i = 0; i < 8; i++) {
                int k = ks + 64 * i;
                p += W2[(size_t)k * 1025 + jj] * W1[(size_t)jj * 513 + k];
            }
        }
        cred[(tid >> 6) * 64 + ks] = p;
    }
    __syncthreads();
    if (tid < 4) {
        int jj = s * 4 + tid;
        if (jj < N1) {
            float ssum = 0.f;
            for (int i = 0; i < 64; i++) ssum += cred[tid * 64 + i];
            g_c[jj] = ssum;
            float t0 = t[0];
            g_beff1[jj] = b1[jj] + t0 * W1[(size_t)jj * 513 + 512];
            if (jj < N2) g_beff2[jj] = b2[jj] + t0 * W2[(size_t)jj * 1025 + 1024];
        }
    }
    __syncthreads();
    __threadfence();
    if (tid == 0) atomicAdd(&g_prep_done, 1);
}

// ---------------- unified 128x128 FFMA tile (R10/R13 body) ------------------
// MODE 0: relu(acc+bias) -> outp      (G1)
// MODE 1: acc+bias -> outp            (G2 halfA)     TRACE: store +partial
// MODE 2: outp += acc                 (G2 halfB)     TRACE: negate-sum
// MODE 3: acc -> outp (raw, no bias)  (G2 quarter)   TRACE: store +partial
template<int MODE, bool TRACE>
__device__ __forceinline__ void gemm_tile(
    float* As, float* Bs,
    const float* __restrict__ A, const float* __restrict__ Bw,
    float* __restrict__ outp, const float* __restrict__ bias,
    const float* __restrict__ cbase,
    int Kloop, int lda, int ldc, int m0, int n0,
    float* __restrict__ trace_out, int tid)
{
    const int lrow = tid >> 1;
    const int lk4  = (tid & 1) << 2;
    const float* Ap = A  + (size_t)(m0 + lrow) * lda + lk4;
    const float* Bp = Bw + (size_t)(n0 + lrow) * lda + lk4;
    const int tx = tid & 15;
    const int ty = tid >> 4;

    float acc[8][8];
    #pragma unroll
    for (int i = 0; i < 8; i++)
        #pragma unroll
        for (int j = 0; j < 8; j++) acc[i][j] = 0.f;

    float tr = 0.f;
    float4 av = *(const float4*)Ap;
    float4 bv = *(const float4*)Bp;

    for (int k0 = 0; k0 < Kloop; k0 += 8) {
        As[(lk4 + 0) * 128 + lrow] = av.x;
        As[(lk4 + 1) * 128 + lrow] = av.y;
        As[(lk4 + 2) * 128 + lrow] = av.z;
        As[(lk4 + 3) * 128 + lrow] = av.w;
        Bs[(lk4 + 0) * 128 + lrow] = bv.x;
        Bs[(lk4 + 1) * 128 + lrow] = bv.y;
        Bs[(lk4 + 2) * 128 + lrow] = bv.z;
        Bs[(lk4 + 3) * 128 + lrow] = bv.w;

        if (TRACE) {
            const float4 cv = *(const float4*)(cbase + k0 + lk4);
            tr += (av.x > 0.f) ? cv.x : 0.f;
            tr += (av.y > 0.f) ? cv.y : 0.f;
            tr += (av.z > 0.f) ? cv.z : 0.f;
            tr += (av.w > 0.f) ? cv.w : 0.f;
        }
        __syncthreads();
        if (k0 + 8 < Kloop) {
            av = *(const float4*)(Ap + k0 + 8);
            bv = *(const float4*)(Bp + k0 + 8);
        }
        #pragma unroll
        for (int kk = 0; kk < 8; kk++) {
            float4 a0 = *(const float4*)&As[kk * 128 + ty * 4];
            float4 a1 = *(const float4*)&As[kk * 128 + ty * 4 + 64];
            float4 b0 = *(const float4*)&Bs[kk * 128 + tx * 4];
            float4 b1 = *(const float4*)&Bs[kk * 128 + tx * 4 + 64];
            float a[8] = {a0.x, a0.y, a0.z, a0.w, a1.x, a1.y, a1.z, a1.w};
            float b[8] = {b0.x, b0.y, b0.z, b0.w, b1.x, b1.y, b1.z, b1.w};
            #pragma unroll
            for (int i = 0; i < 8; i++)
                #pragma unroll
                for (int j = 0; j < 8; j++)
                    acc[i][j] += a[i] * b[j];
        }
        __syncthreads();
    }

    #pragma unroll
    for (int i = 0; i < 8; i++) {
        int m = m0 + ty * 4 + (i & 3) + ((i >= 4) ? 64 : 0);
        float* cp = outp + (size_t)m * ldc + n0 + tx * 4;
        if (MODE == 2) {
            float4 o0 = *(const float4*)cp;
            float4 o1 = *(const float4*)(cp + 64);
            o0.x += acc[i][0]; o0.y += acc[i][1];
            o0.z += acc[i][2]; o0.w += acc[i][3];
            o1.x += acc[i][4]; o1.y += acc[i][5];
            o1.z += acc[i][6]; o1.w += acc[i][7];
            *(float4*)cp        = o0;
            *(float4*)(cp + 64) = o1;
        } else if (MODE == 3) {
            *(float4*)cp        = make_float4(acc[i][0], acc[i][1], acc[i][2], acc[i][3]);
            *(float4*)(cp + 64) = make_float4(acc[i][4], acc[i][5], acc[i][6], acc[i][7]);
        } else {
            const float4 be0 = *(const float4*)(bias + n0 + tx * 4);
            const float4 be1 = *(const float4*)(bias + n0 + 64 + tx * 4);
            float v[8];
            v[0] = acc[i][0] + be0.x; v[1] = acc[i][1] + be0.y;
            v[2] = acc[i][2] + be0.z; v[3] = acc[i][3] + be0.w;
            v[4] = acc[i][4] + be1.x; v[5] = acc[i][5] + be1.y;
            v[6] = acc[i][6] + be1.z; v[7] = acc[i][7] + be1.w;
            if (MODE == 0) {
                #pragma unroll
                for (int j = 0; j < 8; j++) v[j] = fmaxf(v[j], 0.f);
            }
            *(float4*)cp        = make_float4(v[0], v[1], v[2], v[3]);
            *(float4*)(cp + 64) = make_float4(v[4], v[5], v[6], v[7]);
        }
    }
    if (TRACE) {
        float tro = __shfl_xor_sync(0xffffffffu, tr, 1);
        if ((tid & 1) == 0) {
            float part = tr + tro;
            if (MODE == 2) trace_out[m0 + lrow] = -(trace_out[m0 + lrow] + part);
            else           trace_out[m0 + lrow] = part;     // MODE 1 / 3: +partial
        }
    }
}

// ---------------- persistent fused kernel ----------------------------------
__global__ void __launch_bounds__(256, 2)
fused(const float* __restrict__ z, float* __restrict__ out,
      const float* __restrict__ t,
      const float* __restrict__ W1, const float* __restrict__ b1,
      const float* __restrict__ W2, const float* __restrict__ b2) {
    __shared__ float As[8 * 128];
    __shared__ float Bs[8 * 128];
    __shared__ int s_t;
    const int tid = threadIdx.x;
    float* trace_out = out + (size_t)NB * N2;

    for (;;) {
        __syncthreads();
        if (tid == 0) s_t = atomicAdd(&g_q, 1);
        __syncthreads();
        const int tq = s_t;
        if (tq >= NTILES) return;

        if (tq < NPREP) {
            prep_slice(tq, tid, As, t, W1, b1, W2, b2);
        } else if (tq < T2AB) {
            // ---- G1 tile ----
            if (tid == 0)
                while (*(volatile int*)&g_prep_done < NPREP) __nanosleep(40);
            __syncthreads();
            __threadfence();
            const int u = tq - T1B;
            const int yt = u >> 3, xt = u & 7;
            gemm_tile<0, false>(As, Bs, z, g_W1p, g_h, g_beff1, g_c,
                                K1, K1, N1, yt * 128, xt * 128, nullptr, tid);
            __threadfence();
            __syncthreads();
            if (tid == 0) atomicAdd(&g_ready[yt], 1);
        } else if (tq < T2BB) {
            // ---- G2 halfA (u < 320): k 0..511, stores acc+bias ----
            const int u = tq - T2AB;
            const int yt = u >> 2, xt = u & 3;
            if (tid == 0)
                while (*(volatile int*)&g_ready[yt] < 8) __nanosleep(40);
            __syncthreads();
            __threadfence();
            if (xt == 0)
                gemm_tile<1, true>(As, Bs, g_h, g_W2p, out, g_beff2, g_c,
                                   512, K2, N2, yt * 128, 0, trace_out, tid);
            else
                gemm_tile<1, false>(As, Bs, g_h, g_W2p, out, g_beff2, g_c,
                                    512, K2, N2, yt * 128, xt * 128, nullptr, tid);
            __threadfence();
            __syncthreads();
            if (tid == 0) atomicExch(&g_half[u], 1);
        } else if (tq < QB) {
            // ---- G2 halfB (u < 320): k 512..1023, adds into out ----
            const int u = tq - T2BB;
            const int yt = u >> 2, xt = u & 3;
            if (tid == 0)
                while (*(volatile int*)&g_half[u] == 0) __nanosleep(40);
            __syncthreads();
            __threadfence();
            if (xt == 0)
                gemm_tile<2, true>(As, Bs, g_h + 512, g_W2p + 512, out, g_beff2,
                                   g_c + 512, 512, K2, N2, yt * 128, 0,
                                   trace_out, tid);
            else
                gemm_tile<2, false>(As, Bs, g_h + 512, g_W2p + 512, out, g_beff2,
                                    g_c + 512, 512, K2, N2, yt * 128, xt * 128,
                                    nullptr, tid);
        } else if (tq < CB) {
            // ---- G2 quarter (u >= 320): k-quarter qi, raw partial -> g_p[qi]
            const int i  = tq - QB;
            const int uq = i >> 2, qi = i & 3;
            const int u  = NHALF + uq;
            const int yt = u >> 2, xt = u & 3;
            const int ko = qi * 256;
            if (tid == 0)
                while (*(volatile int*)&g_ready[yt] < 8) __nanosleep(40);
            __syncthreads();
            __threadfence();
            if (xt == 0)
                gemm_tile<3, true>(As, Bs, g_h + ko, g_W2p + ko, g_p[qi], nullptr,
                                   g_c + ko, 256, K2, N2, yt * 128, 0,
                                   g_tq[qi], tid);
            else
                gemm_tile<3, false>(As, Bs, g_h + ko, g_W2p + ko, g_p[qi], nullptr,
                                    g_c + ko, 256, K2, N2, yt * 128, xt * 128,
                                    nullptr, tid);
            __threadfence();
            __syncthreads();
            if (tid == 0) atomicAdd(&g_qc[uq], 1);
        } else {
            // ---- combine: out = ((p0+p1)+(p2+p3)) + bias; trace likewise ----
            const int uq = tq - CB;
            const int u  = NHALF + uq;
            const int yt = u >> 2, xt = u & 3;
            const int m0 = yt * 128, n0 = xt * 128;
            if (tid == 0)
                while (*(volatile int*)&g_qc[uq] < 4) __nanosleep(40);
            __syncthreads();
            __threadfence();
            #pragma unroll
            for (int i = 0; i < 16; i++) {
                int idx = tid + i * 256;              // 4096 float4 positions
                int row = idx >> 5, c4 = idx & 31;
                size_t off = (size_t)(m0 + row) * N2 + n0 + c4 * 4;
                float4 p0 = *(const float4*)(g_p[0] + off);
                float4 p1 = *(const float4*)(g_p[1] + off);
                float4 p2 = *(const float4*)(g_p[2] + off);
                float4 p3 = *(const float4*)(g_p[3] + off);
                float4 be = *(const float4*)(g_beff2 + n0 + c4 * 4);
                float4 o;
                o.x = ((p0.x + p1.x) + (p2.x + p3.x)) + be.x;
                o.y = ((p0.y + p1.y) + (p2.y + p3.y)) + be.y;
                o.z = ((p0.z + p1.z) + (p2.z + p3.z)) + be.z;
                o.w = ((p0.w + p1.w) + (p2.w + p3.w)) + be.w;
                *(float4*)(out + off) = o;
            }
            if (xt == 0 && tid < 128) {
                int r = m0 + tid;
                trace_out[r] = -((g_tq[0][r] + g_tq[1][r]) + (g_tq[2][r] + g_tq[3][r]));
            }
        }
    }
}

// ---------------------------------------------------------------------------
extern "C" void kernel_launch(void* const* d_in, const int* in_sizes, int n_in,
                              void* d_out, int out_size) {
    const float* t  = (const float*)d_in[0];
    const float* z  = (const float*)d_in[1];
    // d_in[2] = logp_z (zeros; unused)
    const float* W1 = (const float*)d_in[3];
    const float* b1 = (const float*)d_in[4];
    const float* W2 = (const float*)d_in[5];
    const float* b2 = (const float*)d_in[6];
    float* out = (float*)d_out;   // dz (NB*512) then dlogp (NB)

    init_k<<<2, 256>>>();
    fused<<<NCTA, 256>>>(z, out, t, W1, b1, W2, b2);
}

// round 15
// speedup vs baseline: 1.0460x; 1.0460x over previous
#include <cuda_runtime.h>

#define NB 16384
#define N1 1024
#define K1 512
#define N2 512
#define K2 1024
#define NCTA 304
#define NPREP 304
#define RPTOT (N1*K1 + N2*K2)        // 1048576 repack elements
#define RPSLICE 3450                 // ceil(RPTOT/304)
#define NT1 1024                     // G1: 128 rowblocks x 8 ntiles (128x128,K512)
#define NT2 512                      // G2 tiles (128x128,K1024) -> 2 halves each
#define T1B  NPREP
#define T2AB (NPREP + NT1)           // G2 halfA region
#define T2BB (NPREP + NT1 + NT2)     // G2 halfB region
#define NTILES (NPREP + NT1 + 2 * NT2)

// ---------------- device-global scratch (no allocations) -------------------
__device__ float g_W1p[N1 * K1];
__device__ float g_W2p[N2 * K2];
__device__ float g_h[(size_t)NB * N1];
__device__ float g_beff1[N1], g_beff2[N2], g_c[N1];
__device__ int   g_q;
__device__ int   g_prep_done;
__device__ int   g_ready[NB / 128];
__device__ int   g_half[NT2];

// ---------------- init (graph-replay-safe reset) ---------------------------
__global__ void init_k() {
    int i = blockIdx.x * 256 + threadIdx.x;
    if (i == 0) { g_q = 0; g_prep_done = 0; }
    if (i < NB / 128) g_ready[i] = 0;
    if (i < NT2) g_half[i] = 0;
}

// ---------------- prep slice (runs inside persistent kernel) ---------------
__device__ void prep_slice(int s, int tid, float* cred,
                           const float* __restrict__ t,
                           const float* __restrict__ W1, const float* __restrict__ b1,
                           const float* __restrict__ W2, const float* __restrict__ b2) {
    // 1) weight repack slice
    int end = min((s + 1) * RPSLICE, RPTOT);
    for (int i = s * RPSLICE + tid; i < end; i += 256) {
        if (i < N1 * K1) {
            int n = i >> 9, k = i & 511;
            g_W1p[i] = W1[n * 513 + k];
        } else {
            int j = i - N1 * K1;
            int n = j >> 10, k = j & 1023;
            g_W2p[j] = W2[n * 1025 + k];
        }
    }
    // 2) c vector: 4 j's per slice, 64 threads each, fixed-order reduce
    {
        int jj = s * 4 + (tid >> 6);
        int ks = tid & 63;
        float p = 0.f;
        if (jj < N1) {
            #pragma unroll
            for (int i = 0; i < 8; i++) {
                int k = ks + 64 * i;
                p += W2[(size_t)k * 1025 + jj] * W1[(size_t)jj * 513 + k];
            }
        }
        cred[(tid >> 6) * 64 + ks] = p;
    }
    __syncthreads();
    if (tid < 4) {
        int jj = s * 4 + tid;
        if (jj < N1) {
            float ssum = 0.f;
            for (int i = 0; i < 64; i++) ssum += cred[tid * 64 + i];
            g_c[jj] = ssum;
            float t0 = t[0];
            g_beff1[jj] = b1[jj] + t0 * W1[(size_t)jj * 513 + 512];
            if (jj < N2) g_beff2[jj] = b2[jj] + t0 * W2[(size_t)jj * 1025 + 1024];
        }
    }
    __syncthreads();
    __threadfence();
    if (tid == 0) atomicAdd(&g_prep_done, 1);
}

// ---------------- unified 128x128 FFMA tile (R10 body, byte-identical loop) -
// MODE 0: relu(acc+bias) -> outp          (G1)
// MODE 1: acc+bias -> outp                (G2 halfA, k 0..Kloop)
// MODE 2: outp += acc                     (G2 halfB)
// TRACE: partial mask@c over this k-range; MODE1 stores +partial, MODE2
// finalizes -(partialA + partialB).
template<int MODE, bool TRACE>
__device__ __forceinline__ void gemm_tile(
    float* As, float* Bs,
    const float* __restrict__ A, const float* __restrict__ Bw,
    float* __restrict__ outp, const float* __restrict__ bias,
    const float* __restrict__ cbase,
    int Kloop, int lda, int ldc, int m0, int n0,
    float* __restrict__ trace_out, int tid)
{
    const int lrow = tid >> 1;
    const int lk4  = (tid & 1) << 2;
    const float* Ap = A  + (size_t)(m0 + lrow) * lda + lk4;
    const float* Bp = Bw + (size_t)(n0 + lrow) * lda + lk4;
    const int tx = tid & 15;
    const int ty = tid >> 4;

    float acc[8][8];
    #pragma unroll
    for (int i = 0; i < 8; i++)
        #pragma unroll
        for (int j = 0; j < 8; j++) acc[i][j] = 0.f;

    float tr = 0.f;
    float4 av = *(const float4*)Ap;
    float4 bv = *(const float4*)Bp;

    for (int k0 = 0; k0 < Kloop; k0 += 8) {
        As[(lk4 + 0) * 128 + lrow] = av.x;
        As[(lk4 + 1) * 128 + lrow] = av.y;
        As[(lk4 + 2) * 128 + lrow] = av.z;
        As[(lk4 + 3) * 128 + lrow] = av.w;
        Bs[(lk4 + 0) * 128 + lrow] = bv.x;
        Bs[(lk4 + 1) * 128 + lrow] = bv.y;
        Bs[(lk4 + 2) * 128 + lrow] = bv.z;
        Bs[(lk4 + 3) * 128 + lrow] = bv.w;

        if (TRACE) {
            const float4 cv = *(const float4*)(cbase + k0 + lk4);
            tr += (av.x > 0.f) ? cv.x : 0.f;
            tr += (av.y > 0.f) ? cv.y : 0.f;
            tr += (av.z > 0.f) ? cv.z : 0.f;
            tr += (av.w > 0.f) ? cv.w : 0.f;
        }
        __syncthreads();
        if (k0 + 8 < Kloop) {
            av = *(const float4*)(Ap + k0 + 8);
            bv = *(const float4*)(Bp + k0 + 8);
        }
        #pragma unroll
        for (int kk = 0; kk < 8; kk++) {
            float4 a0 = *(const float4*)&As[kk * 128 + ty * 4];
            float4 a1 = *(const float4*)&As[kk * 128 + ty * 4 + 64];
            float4 b0 = *(const float4*)&Bs[kk * 128 + tx * 4];
            float4 b1 = *(const float4*)&Bs[kk * 128 + tx * 4 + 64];
            float a[8] = {a0.x, a0.y, a0.z, a0.w, a1.x, a1.y, a1.z, a1.w};
            float b[8] = {b0.x, b0.y, b0.z, b0.w, b1.x, b1.y, b1.z, b1.w};
            #pragma unroll
            for (int i = 0; i < 8; i++)
                #pragma unroll
                for (int j = 0; j < 8; j++)
                    acc[i][j] += a[i] * b[j];
        }
        __syncthreads();
    }

    #pragma unroll
    for (int i = 0; i < 8; i++) {
        int m = m0 + ty * 4 + (i & 3) + ((i >= 4) ? 64 : 0);
        float* cp = outp + (size_t)m * ldc + n0 + tx * 4;
        if (MODE == 2) {
            float4 o0 = *(const float4*)cp;
            float4 o1 = *(const float4*)(cp + 64);
            o0.x += acc[i][0]; o0.y += acc[i][1];
            o0.z += acc[i][2]; o0.w += acc[i][3];
            o1.x += acc[i][4]; o1.y += acc[i][5];
            o1.z += acc[i][6]; o1.w += acc[i][7];
            *(float4*)cp        = o0;
            *(float4*)(cp + 64) = o1;
        } else {
            const float4 be0 = *(const float4*)(bias + n0 + tx * 4);
            const float4 be1 = *(const float4*)(bias + n0 + 64 + tx * 4);
            float v[8];
            v[0] = acc[i][0] + be0.x; v[1] = acc[i][1] + be0.y;
            v[2] = acc[i][2] + be0.z; v[3] = acc[i][3] + be0.w;
            v[4] = acc[i][4] + be1.x; v[5] = acc[i][5] + be1.y;
            v[6] = acc[i][6] + be1.z; v[7] = acc[i][7] + be1.w;
            if (MODE == 0) {
                #pragma unroll
                for (int j = 0; j < 8; j++) v[j] = fmaxf(v[j], 0.f);
            }
            *(float4*)cp        = make_float4(v[0], v[1], v[2], v[3]);
            *(float4*)(cp + 64) = make_float4(v[4], v[5], v[6], v[7]);
        }
    }
    if (TRACE) {
        float tro = __shfl_xor_sync(0xffffffffu, tr, 1);
        if ((tid & 1) == 0) {
            float part = tr + tro;
            if (MODE == 1) trace_out[m0 + lrow] = part;                     // +partialA
            else           trace_out[m0 + lrow] = -(trace_out[m0 + lrow] + part);
        }
    }
}

// ---------------- persistent fused kernel ----------------------------------
__global__ void __launch_bounds__(256, 2)
fused(const float* __restrict__ z, float* __restrict__ out,
      const float* __restrict__ t,
      const float* __restrict__ W1, const float* __restrict__ b1,
      const float* __restrict__ W2, const float* __restrict__ b2) {
    __shared__ float As[8 * 128];
    __shared__ float Bs[8 * 128];
    __shared__ int s_t;
    const int tid = threadIdx.x;
    float* trace_out = out + (size_t)NB * N2;

    for (;;) {
        __syncthreads();
        if (tid == 0) s_t = atomicAdd(&g_q, 1);
        __syncthreads();
        const int tq = s_t;
        if (tq >= NTILES) return;

        if (tq < NPREP) {
            prep_slice(tq, tid, As, t, W1, b1, W2, b2);
        } else if (tq < T2AB) {
            // ---- G1 tile ----
            if (tid == 0)
                while (*(volatile int*)&g_prep_done < NPREP) __nanosleep(40);
            __syncthreads();
            __threadfence();
            const int u = tq - T1B;
            const int yt = u >> 3, xt = u & 7;
            gemm_tile<0, false>(As, Bs, z, g_W1p, g_h, g_beff1, g_c,
                                K1, K1, N1, yt * 128, xt * 128, nullptr, tid);
            __threadfence();                  // release h stores
            __syncthreads();
            if (tid == 0) atomicAdd(&g_ready[yt], 1);
        } else if (tq < T2BB) {
            // ---- G2 halfA: k 0..511, stores acc+bias ----
            const int u = tq - T2AB;
            const int yt = u >> 2, xt = u & 3;
            if (tid == 0)
                while (*(volatile int*)&g_ready[yt] < 8) __nanosleep(40);
            __syncthreads();
            __threadfence();                  // acquire h
            if (xt == 0)
                gemm_tile<1, true>(As, Bs, g_h, g_W2p, out, g_beff2, g_c,
                                   512, K2, N2, yt * 128, 0, trace_out, tid);
            else
                gemm_tile<1, false>(As, Bs, g_h, g_W2p, out, g_beff2, g_c,
                                    512, K2, N2, yt * 128, xt * 128, nullptr, tid);
            __threadfence();                  // release out partials
            __syncthreads();
            if (tid == 0) atomicExch(&g_half[u], 1);
        } else {
            // ---- G2 halfB: k 512..1023, adds into out ----
            const int u = tq - T2BB;
            const int yt = u >> 2, xt = u & 3;
            if (tid == 0)
                while (*(volatile int*)&g_half[u] == 0) __nanosleep(40);
            __syncthreads();
            __threadfence();                  // acquire halfA partials + h
            if (xt == 0)
                gemm_tile<2, true>(As, Bs, g_h + 512, g_W2p + 512, out, g_beff2,
                                   g_c + 512, 512, K2, N2, yt * 128, 0,
                                   trace_out, tid);
            else
                gemm_tile<2, false>(As, Bs, g_h + 512, g_W2p + 512, out, g_beff2,
                                    g_c + 512, 512, K2, N2, yt * 128, xt * 128,
                                    nullptr, tid);
        }
    }
}

// ---------------------------------------------------------------------------
extern "C" void kernel_launch(void* const* d_in, const int* in_sizes, int n_in,
                              void* d_out, int out_size) {
    const float* t  = (const float*)d_in[0];
    const float* z  = (const float*)d_in[1];
    // d_in[2] = logp_z (zeros; unused)
    const float* W1 = (const float*)d_in[3];
    const float* b1 = (const float*)d_in[4];
    const float* W2 = (const float*)d_in[5];
    const float* b2 = (const float*)d_in[6];
    float* out = (float*)d_out;   // dz (NB*512) then dlogp (NB)

    init_k<<<2, 256>>>();
    fused<<<NCTA, 256>>>(z, out, t, W1, b1, W2, b2);
}

// round 16
// speedup vs baseline: 1.0512x; 1.0049x over previous
#include <cuda_runtime.h>

#define NB 16384
#define N1 1024
#define K1 512
#define N2 512
#define K2 1024
#define NCTA 304
#define NPREP 304
#define RPTOT (N1*K1 + N2*K2)        // 1048576 repack elements
#define RPSLICE 3450                 // ceil(RPTOT/304)
#define NT1 1024                     // G1: 128 rowblocks x 8 ntiles (128x128,K512)
#define NT2 512                      // G2 tiles (128x128,K1024) -> 2 halves each
#define T1B  NPREP
#define T2AB (NPREP + NT1)           // G2 halfA region
#define T2BB (NPREP + NT1 + NT2)     // G2 halfB region
#define NTILES (NPREP + NT1 + 2 * NT2)

// ---------------- device-global scratch (no allocations) -------------------
// zero-initialized at module load; persistent kernel self-resets at end of
// each run so graph replays see clean state without an extra init launch.
__device__ float g_W1p[N1 * K1];
__device__ float g_W2p[N2 * K2];
__device__ float g_h[(size_t)NB * N1];
__device__ float g_beff1[N1], g_beff2[N2], g_c[N1];
__device__ int   g_q;
__device__ int   g_prep_done;
__device__ int   g_done;
__device__ int   g_ready[NB / 128];
__device__ int   g_half[NT2];

// ---------------- prep slice (runs inside persistent kernel) ---------------
__device__ void prep_slice(int s, int tid, float* cred,
                           const float* __restrict__ t,
                           const float* __restrict__ W1, const float* __restrict__ b1,
                           const float* __restrict__ W2, const float* __restrict__ b2) {
    // 1) weight repack slice
    int end = min((s + 1) * RPSLICE, RPTOT);
    for (int i = s * RPSLICE + tid; i < end; i += 256) {
        if (i < N1 * K1) {
            int n = i >> 9, k = i & 511;
            g_W1p[i] = W1[n * 513 + k];
        } else {
            int j = i - N1 * K1;
            int n = j >> 10, k = j & 1023;
            g_W2p[j] = W2[n * 1025 + k];
        }
    }
    // 2) c vector: 4 j's per slice, 64 threads each, fixed-order reduce
    {
        int jj = s * 4 + (tid >> 6);
        int ks = tid & 63;
        float p = 0.f;
        if (jj < N1) {
            #pragma unroll
            for (int i = 0; i < 8; i++) {
                int k = ks + 64 * i;
                p += W2[(size_t)k * 1025 + jj] * W1[(size_t)jj * 513 + k];
            }
        }
        cred[(tid >> 6) * 64 + ks] = p;
    }
    __syncthreads();
    if (tid < 4) {
        int jj = s * 4 + tid;
        if (jj < N1) {
            float ssum = 0.f;
            for (int i = 0; i < 64; i++) ssum += cred[tid * 64 + i];
            g_c[jj] = ssum;
            float t0 = t[0];
            g_beff1[jj] = b1[jj] + t0 * W1[(size_t)jj * 513 + 512];
            if (jj < N2) g_beff2[jj] = b2[jj] + t0 * W2[(size_t)jj * 1025 + 1024];
        }
    }
    __syncthreads();
    __threadfence();
    if (tid == 0) atomicAdd(&g_prep_done, 1);
}

// ---------------- unified 128x128 FFMA tile (R10 body, byte-identical loop) -
// MODE 0: relu(acc+bias) -> outp          (G1)
// MODE 1: acc+bias -> outp                (G2 halfA, k 0..Kloop)
// MODE 2: outp += acc                     (G2 halfB)
// TRACE: partial mask@c over this k-range; MODE1 stores +partial, MODE2
// finalizes -(partialA + partialB).
template<int MODE, bool TRACE>
__device__ __forceinline__ void gemm_tile(
    float* As, float* Bs,
    const float* __restrict__ A, const float* __restrict__ Bw,
    float* __restrict__ outp, const float* __restrict__ bias,
    const float* __restrict__ cbase,
    int Kloop, int lda, int ldc, int m0, int n0,
    float* __restrict__ trace_out, int tid)
{
    const int lrow = tid >> 1;
    const int lk4  = (tid & 1) << 2;
    const float* Ap = A  + (size_t)(m0 + lrow) * lda + lk4;
    const float* Bp = Bw + (size_t)(n0 + lrow) * lda + lk4;
    const int tx = tid & 15;
    const int ty = tid >> 4;

    float acc[8][8];
    #pragma unroll
    for (int i = 0; i < 8; i++)
        #pragma unroll
        for (int j = 0; j < 8; j++) acc[i][j] = 0.f;

    float tr = 0.f;
    float4 av = *(const float4*)Ap;
    float4 bv = *(const float4*)Bp;

    for (int k0 = 0; k0 < Kloop; k0 += 8) {
        As[(lk4 + 0) * 128 + lrow] = av.x;
        As[(lk4 + 1) * 128 + lrow] = av.y;
        As[(lk4 + 2) * 128 + lrow] = av.z;
        As[(lk4 + 3) * 128 + lrow] = av.w;
        Bs[(lk4 + 0) * 128 + lrow] = bv.x;
        Bs[(lk4 + 1) * 128 + lrow] = bv.y;
        Bs[(lk4 + 2) * 128 + lrow] = bv.z;
        Bs[(lk4 + 3) * 128 + lrow] = bv.w;

        if (TRACE) {
            const float4 cv = *(const float4*)(cbase + k0 + lk4);
            tr += (av.x > 0.f) ? cv.x : 0.f;
            tr += (av.y > 0.f) ? cv.y : 0.f;
            tr += (av.z > 0.f) ? cv.z : 0.f;
            tr += (av.w > 0.f) ? cv.w : 0.f;
        }
        __syncthreads();
        if (k0 + 8 < Kloop) {
            av = *(const float4*)(Ap + k0 + 8);
            bv = *(const float4*)(Bp + k0 + 8);
        }
        #pragma unroll
        for (int kk = 0; kk < 8; kk++) {
            float4 a0 = *(const float4*)&As[kk * 128 + ty * 4];
            float4 a1 = *(const float4*)&As[kk * 128 + ty * 4 + 64];
            float4 b0 = *(const float4*)&Bs[kk * 128 + tx * 4];
            float4 b1 = *(const float4*)&Bs[kk * 128 + tx * 4 + 64];
            float a[8] = {a0.x, a0.y, a0.z, a0.w, a1.x, a1.y, a1.z, a1.w};
            float b[8] = {b0.x, b0.y, b0.z, b0.w, b1.x, b1.y, b1.z, b1.w};
            #pragma unroll
            for (int i = 0; i < 8; i++)
                #pragma unroll
                for (int j = 0; j < 8; j++)
                    acc[i][j] += a[i] * b[j];
        }
        __syncthreads();
    }

    #pragma unroll
    for (int i = 0; i < 8; i++) {
        int m = m0 + ty * 4 + (i & 3) + ((i >= 4) ? 64 : 0);
        float* cp = outp + (size_t)m * ldc + n0 + tx * 4;
        if (MODE == 2) {
            float4 o0 = *(const float4*)cp;
            float4 o1 = *(const float4*)(cp + 64);
            o0.x += acc[i][0]; o0.y += acc[i][1];
            o0.z += acc[i][2]; o0.w += acc[i][3];
            o1.x += acc[i][4]; o1.y += acc[i][5];
            o1.z += acc[i][6]; o1.w += acc[i][7];
            *(float4*)cp        = o0;
            *(float4*)(cp + 64) = o1;
        } else {
            const float4 be0 = *(const float4*)(bias + n0 + tx * 4);
            const float4 be1 = *(const float4*)(bias + n0 + 64 + tx * 4);
            float v[8];
            v[0] = acc[i][0] + be0.x; v[1] = acc[i][1] + be0.y;
            v[2] = acc[i][2] + be0.z; v[3] = acc[i][3] + be0.w;
            v[4] = acc[i][4] + be1.x; v[5] = acc[i][5] + be1.y;
            v[6] = acc[i][6] + be1.z; v[7] = acc[i][7] + be1.w;
            if (MODE == 0) {
                #pragma unroll
                for (int j = 0; j < 8; j++) v[j] = fmaxf(v[j], 0.f);
            }
            *(float4*)cp        = make_float4(v[0], v[1], v[2], v[3]);
            *(float4*)(cp + 64) = make_float4(v[4], v[5], v[6], v[7]);
        }
    }
    if (TRACE) {
        float tro = __shfl_xor_sync(0xffffffffu, tr, 1);
        if ((tid & 1) == 0) {
            float part = tr + tro;
            if (MODE == 1) trace_out[m0 + lrow] = part;                     // +partialA
            else           trace_out[m0 + lrow] = -(trace_out[m0 + lrow] + part);
        }
    }
}

// ---------------- persistent fused kernel ----------------------------------
__global__ void __launch_bounds__(256, 2)
fused(const float* __restrict__ z, float* __restrict__ out,
      const float* __restrict__ t,
      const float* __restrict__ W1, const float* __restrict__ b1,
      const float* __restrict__ W2, const float* __restrict__ b2) {
    __shared__ float As[8 * 128];
    __shared__ float Bs[8 * 128];
    __shared__ int s_t;
    const int tid = threadIdx.x;
    float* trace_out = out + (size_t)NB * N2;

    for (;;) {
        __syncthreads();
        if (tid == 0) s_t = atomicAdd(&g_q, 1);
        __syncthreads();
        const int tq = s_t;
        if (tq >= NTILES) break;

        if (tq < NPREP) {
            prep_slice(tq, tid, As, t, W1, b1, W2, b2);
        } else if (tq < T2AB) {
            // ---- G1 tile ----
            if (tid == 0)
                while (*(volatile int*)&g_prep_done < NPREP) __nanosleep(40);
            __syncthreads();
            __threadfence();
            const int u = tq - T1B;
            const int yt = u >> 3, xt = u & 7;
            gemm_tile<0, false>(As, Bs, z, g_W1p, g_h, g_beff1, g_c,
                                K1, K1, N1, yt * 128, xt * 128, nullptr, tid);
            __threadfence();                  // release h stores
            __syncthreads();
            if (tid == 0) atomicAdd(&g_ready[yt], 1);
        } else if (tq < T2BB) {
            // ---- G2 halfA: k 0..511, stores acc+bias ----
            const int u = tq - T2AB;
            const int yt = u >> 2, xt = u & 3;
            if (tid == 0)
                while (*(volatile int*)&g_ready[yt] < 8) __nanosleep(40);
            __syncthreads();
            __threadfence();                  // acquire h
            if (xt == 0)
                gemm_tile<1, true>(As, Bs, g_h, g_W2p, out, g_beff2, g_c,
                                   512, K2, N2, yt * 128, 0, trace_out, tid);
            else
                gemm_tile<1, false>(As, Bs, g_h, g_W2p, out, g_beff2, g_c,
                                    512, K2, N2, yt * 128, xt * 128, nullptr, tid);
            __threadfence();                  // release out partials
            __syncthreads();
            if (tid == 0) atomicExch(&g_half[u], 1);
        } else {
            // ---- G2 halfB: k 512..1023, adds into out ----
            const int u = tq - T2BB;
            const int yt = u >> 2, xt = u & 3;
            if (tid == 0)
                while (*(volatile int*)&g_half[u] == 0) __nanosleep(40);
            __syncthreads();
            __threadfence();                  // acquire halfA partials + h
            if (xt == 0)
                gemm_tile<2, true>(As, Bs, g_h + 512, g_W2p + 512, out, g_beff2,
                                   g_c + 512, 512, K2, N2, yt * 128, 0,
                                   trace_out, tid);
            else
                gemm_tile<2, false>(As, Bs, g_h + 512, g_W2p + 512, out, g_beff2,
                                    g_c + 512, 512, K2, N2, yt * 128, xt * 128,
                                    nullptr, tid);
        }
    }

    // ---- epilogue: last CTA to drain the queue resets state for the next
    // graph replay (replaces the init_k launch). Kernel-boundary fence
    // publishes the reset before any subsequent launch.
    __syncthreads();
    if (tid == 0) s_t = atomicAdd(&g_done, 1);
    __syncthreads();
    if (s_t == NCTA - 1) {
        for (int i = tid; i < NT2; i += 256) g_half[i] = 0;
        for (int i = tid; i < NB / 128; i += 256) g_ready[i] = 0;
        if (tid == 0) { g_q = 0; g_prep_done = 0; g_done = 0; }
        __threadfence();
    }
}

// ---------------------------------------------------------------------------
extern "C" void kernel_launch(void* const* d_in, const int* in_sizes, int n_in,
                              void* d_out, int out_size) {
    const float* t  = (const float*)d_in[0];
    const float* z  = (const float*)d_in[1];
    // d_in[2] = logp_z (zeros; unused)
    const float* W1 = (const float*)d_in[3];
    const float* b1 = (const float*)d_in[4];
    const float* W2 = (const float*)d_in[5];
    const float* b2 = (const float*)d_in[6];
    float* out = (float*)d_out;   // dz (NB*512) then dlogp (NB)

    fused<<<NCTA, 256>>>(z, out, t, W1, b1, W2, b2);
}